// round 3
// baseline (speedup 1.0000x reference)
#include <cuda_runtime.h>
#include <cstdint>
#include <cstddef>

// ---------------- constants ----------------
#define NSEG        2368
#define NSEG_L1     2048          // layer1: m(2) x o(128) x chunk(8), 128 cols each
#define SEG_W2      2048          // +128 segs, 512 cols
#define SEG_W3      2176          // +64 segs, 128 cols
#define SEG_WOUT    2240          // +128 segs, 64 cols
#define LIST_MAX    360448        // fully dense upper bound + padding slack
#define LIST_SM     12288         // smem staging capacity (entries)
#define ACTS        1.3333333730697632f

// ---------------- device scratch ----------------
__device__ int   d_scale_bits[5];
__device__ int   d_cnt[NSEG];
__device__ int   d_off[NSEG + 1];
__device__ __align__(16) short d_list[LIST_MAX];

// ---------------- prep: init ----------------
__global__ void prep_init() {
    if (threadIdx.x < 5) d_scale_bits[threadIdx.x] = 0;
}

// ---------------- prep: per-tensor max|w| ----------------
__global__ void prep_scale(const float* __restrict__ W1a, const float* __restrict__ W1b,
                           const float* __restrict__ W2,  const float* __restrict__ W3,
                           const float* __restrict__ Wout)
{
    __shared__ float red[8];
    int m = blockIdx.x >> 5;
    int part = blockIdx.x & 31;
    const float* W; int n;
    switch (m) {
        case 0: W = W1a;  n = 131072; break;
        case 1: W = W1b;  n = 131072; break;
        case 2: W = W2;   n = 65536;  break;
        case 3: W = W3;   n = 8192;   break;
        default: W = Wout; n = 8192;  break;
    }
    int chunk = n >> 5;
    int lo = part * chunk;
    float mx = 0.0f;
    for (int i = lo + threadIdx.x; i < lo + chunk; i += 256)
        mx = fmaxf(mx, fabsf(W[i]));
    #pragma unroll
    for (int o = 16; o; o >>= 1) mx = fmaxf(mx, __shfl_xor_sync(0xffffffffu, mx, o));
    if ((threadIdx.x & 31) == 0) red[threadIdx.x >> 5] = mx;
    __syncthreads();
    if (threadIdx.x < 32) {
        float v = (threadIdx.x < 8) ? red[threadIdx.x] : 0.0f;
        #pragma unroll
        for (int o = 4; o; o >>= 1) v = fmaxf(v, __shfl_xor_sync(0xffffffffu, v, o));
        if (threadIdx.x == 0) atomicMax(&d_scale_bits[m], __float_as_int(v));
    }
}

// ---------------- segment decode ----------------
struct SegInfo { const float* rowp; int len; float s; int stride; };

__device__ __forceinline__ SegInfo seg_decode(int seg,
    const float* W1a, const float* W1b, const float* W2,
    const float* W3, const float* Wout)
{
    SegInfo r;
    if (seg < NSEG_L1) {
        int m = seg >> 10, rem = seg & 1023;
        int o = rem >> 3, c = rem & 7;
        r.rowp = (m ? W1b : W1a) + o * 1024 + c * 128;
        r.len = 128; r.s = __int_as_float(d_scale_bits[m]); r.stride = 33;
    } else if (seg < SEG_W3) {
        r.rowp = W2 + (seg - SEG_W2) * 512;
        r.len = 512; r.s = __int_as_float(d_scale_bits[2]); r.stride = 1;
    } else if (seg < SEG_WOUT) {
        r.rowp = W3 + (seg - SEG_W3) * 128;
        r.len = 128; r.s = __int_as_float(d_scale_bits[3]); r.stride = 1;
    } else {
        r.rowp = Wout + (seg - SEG_WOUT) * 64;
        r.len = 64; r.s = __int_as_float(d_scale_bits[4]); r.stride = 1;
    }
    return r;
}

// ---------------- prep: count nnz per segment, padded to multiple of 4 ----------------
__global__ void prep_count(const float* __restrict__ W1a, const float* __restrict__ W1b,
                           const float* __restrict__ W2,  const float* __restrict__ W3,
                           const float* __restrict__ Wout)
{
    int lane = threadIdx.x & 31;
    int seg = blockIdx.x * 8 + (threadIdx.x >> 5);
    if (seg >= NSEG) return;
    SegInfo si = seg_decode(seg, W1a, W1b, W2, W3, Wout);
    int cnt = 0;
    for (int j0 = 0; j0 < si.len; j0 += 32) {
        float w = si.rowp[j0 + lane];
        float q = rintf(__fdiv_rn(w, si.s));
        unsigned bal = __ballot_sync(0xffffffffu, q != 0.0f);
        cnt += __popc(bal);
    }
    if (lane == 0) d_cnt[seg] = (cnt + 3) & ~3;   // pad to 4
}

// ---------------- prep: exclusive scan (warp-shuffle, 1 block) ----------------
__global__ void prep_scan() {
    __shared__ int warpsum[32];
    int tid = threadIdx.x;
    int lane = tid & 31, w = tid >> 5;
    int base = tid * 3;
    int v[3]; int s = 0;
    #pragma unroll
    for (int k = 0; k < 3; k++) {
        int idx = base + k;
        int c = (idx < NSEG) ? d_cnt[idx] : 0;
        v[k] = s; s += c;
    }
    int incl = s;
    #pragma unroll
    for (int o = 1; o < 32; o <<= 1) {
        int t = __shfl_up_sync(0xffffffffu, incl, o);
        if (lane >= o) incl += t;
    }
    if (lane == 31) warpsum[w] = incl;
    __syncthreads();
    if (w == 0) {
        int ws = warpsum[lane];
        #pragma unroll
        for (int o = 1; o < 32; o <<= 1) {
            int t = __shfl_up_sync(0xffffffffu, ws, o);
            if (lane >= o) ws += t;
        }
        warpsum[lane] = ws;
    }
    __syncthreads();
    int excl = incl - s + (w ? warpsum[w - 1] : 0);
    #pragma unroll
    for (int k = 0; k < 3; k++) {
        int idx = base + k;
        if (idx <= NSEG) d_off[idx] = excl + v[k];
    }
}

// ---------------- prep: fill padded compacted lists ----------------
// entry = (idx*stride)<<2 | wclass ; wclass: 1=+s, 2=-s, 0=pad(zero weight)
__global__ void prep_fill(const float* __restrict__ W1a, const float* __restrict__ W1b,
                          const float* __restrict__ W2,  const float* __restrict__ W3,
                          const float* __restrict__ Wout)
{
    int lane = threadIdx.x & 31;
    int seg = blockIdx.x * 8 + (threadIdx.x >> 5);
    if (seg >= NSEG) return;
    SegInfo si = seg_decode(seg, W1a, W1b, W2, W3, Wout);
    int base = d_off[seg];
    for (int j0 = 0; j0 < si.len; j0 += 32) {
        float w = si.rowp[j0 + lane];
        float q = rintf(__fdiv_rn(w, si.s));
        bool nz = (q != 0.0f);
        unsigned bal = __ballot_sync(0xffffffffu, nz);
        if (nz) {
            int pos = base + __popc(bal & ((1u << lane) - 1u));
            int idx = j0 + lane;
            int e = ((idx * si.stride) << 2) | (q > 0.0f ? 1 : 2);
            d_list[pos] = (short)e;
        }
        base += __popc(bal);
    }
    int end = d_off[seg + 1];
    for (int p = base + lane; p < end; p += 32) d_list[p] = 0;
}

// ---------------- main kernel ----------------
// smem layout (bytes), all offsets 8-aligned:
//  XS0  @ 0      : 128*33*4 = 16896
//  XS1  @ 16896  : 16896
//  H1   @ 33792  : 32*516   = 16512
//  H2   @ 50304  : 32*132   = 4224
//  H3   @ 54528  : 32*68    = 2176
//  OFF  @ 56704  : 2369*4   = 9476
//  LIST @ 66184  : 12288*2  = 24576   -> total 90760 ; OUTS aliases XS0
#define SMEM_BYTES 90760

__device__ __forceinline__ float wsel(unsigned c, float sc) {
    float w = (c == 1u) ? sc : 0.0f;
    return (c == 2u) ? -sc : w;
}
__device__ __forceinline__ int csel(unsigned c, int v) {
    int r = (c == 1u) ? v : 0;
    return (c == 2u) ? -v : r;
}

__device__ __forceinline__ void cp4(unsigned dst, const float* src) {
    asm volatile("cp.async.ca.shared.global [%0], [%1], 4;" :: "r"(dst), "l"(src));
}
__device__ __forceinline__ void cp_commit() {
    asm volatile("cp.async.commit_group;" ::: "memory");
}
__device__ __forceinline__ void cp_wait0() {
    asm volatile("cp.async.wait_group 0;" ::: "memory");
}

__device__ __forceinline__ void mlp_body(
    const short* __restrict__ lst,
    const int*   __restrict__ s_off,
    float* xs0, float* xs1,
    unsigned char* h1s, unsigned char* h2s, unsigned char* h3s,
    float* outs,
    const float* __restrict__ x,
    const float* __restrict__ b1a, const float* __restrict__ b1b,
    const float* __restrict__ b2,  const float* __restrict__ b3,
    float* __restrict__ out,
    int row0, int tid, int r, int g,
    float sc1a, float sc1b, float s2, float s3, float s4)
{
    unsigned xs0a = (unsigned)__cvta_generic_to_shared(xs0);
    unsigned xs1a = (unsigned)__cvta_generic_to_shared(xs1);

    float acc[8];
    #pragma unroll
    for (int j = 0; j < 8; j++) acc[j] = 0.0f;

    // ---- layer 1: 32 tiles of [32 rows x 128 cols] ----
    for (int t = 0; t < 32; ++t) {
        const int branch = t >> 3, chunk = t & 7, m = branch & 1;

        if (t + 1 < 32) {     // async prefetch next tile
            int nb = (t + 1) >> 3, nc = (t + 1) & 7;
            unsigned nxt = (t & 1) ? xs0a : xs1a;
            const float* xb = x + (size_t)row0 * 4096 + nb * 1024 + nc * 128;
            #pragma unroll
            for (int k = 0; k < 8; k++) {
                int i = tid + (k << 9); int rr = i >> 7; int cc = i & 127;
                cp4(nxt + (unsigned)((cc * 33 + rr) << 2), xb + (size_t)rr * 4096 + cc);
            }
            cp_commit();
        }

        const float* cur = (t & 1) ? xs1 : xs0;
        const float  sc  = m ? sc1b : sc1a;
        #pragma unroll
        for (int j = 0; j < 8; j++) {
            int o  = (g << 3) + j;
            int seg = (m << 10) + (o << 3) + chunk;
            int p0 = s_off[seg], p1 = s_off[seg + 1];
            float a = acc[j];
            for (int p = p0; p < p1; p += 4) {
                uint2 pk = *(const uint2*)(lst + p);
                unsigned e0 = pk.x & 0xffffu, e1 = pk.x >> 16;
                unsigned e2 = pk.y & 0xffffu, e3 = pk.y >> 16;
                float x0 = cur[(e0 >> 2) + r];
                float x1 = cur[(e1 >> 2) + r];
                float x2 = cur[(e2 >> 2) + r];
                float x3 = cur[(e3 >> 2) + r];
                a = fmaf(wsel(e0 & 3u, sc), x0, a);
                a = fmaf(wsel(e1 & 3u, sc), x1, a);
                a = fmaf(wsel(e2 & 3u, sc), x2, a);
                a = fmaf(wsel(e3 & 3u, sc), x3, a);
            }
            acc[j] = a;
        }

        if (chunk == 7) {
            const float* bb = m ? b1b : b1a;
            #pragma unroll
            for (int j = 0; j < 8; j++) {
                int o = (g << 3) + j;
                float y = acc[j] + bb[o];
                float qv = rintf(__fdiv_rn(y, ACTS));
                qv = fminf(fmaxf(qv, 0.0f), 3.0f);
                h1s[r * 516 + (branch << 7) + o] = (unsigned char)(int)qv;
                acc[j] = 0.0f;
            }
        }
        if (t + 1 < 32) cp_wait0();
        __syncthreads();
    }

    // ---- layer 2: 512 -> 128 ----
    {
        const unsigned char* hr = h1s + r * 516;
        #pragma unroll
        for (int j = 0; j < 8; j++) {
            int o = (g << 3) + j;
            int seg = SEG_W2 + o;
            int p0 = s_off[seg], p1 = s_off[seg + 1];
            int is = 0;
            for (int p = p0; p < p1; p += 4) {
                uint2 pk = *(const uint2*)(lst + p);
                unsigned e0 = pk.x & 0xffffu, e1 = pk.x >> 16;
                unsigned e2 = pk.y & 0xffffu, e3 = pk.y >> 16;
                int c0 = hr[e0 >> 2], c1 = hr[e1 >> 2];
                int c2 = hr[e2 >> 2], c3 = hr[e3 >> 2];
                is += csel(e0 & 3u, c0) + csel(e1 & 3u, c1)
                    + csel(e2 & 3u, c2) + csel(e3 & 3u, c3);
            }
            float y = fmaf((float)is * ACTS, s2, b2[o]);
            float qv = rintf(__fdiv_rn(y, ACTS));
            qv = fminf(fmaxf(qv, 0.0f), 3.0f);
            h2s[r * 132 + o] = (unsigned char)(int)qv;
        }
    }
    __syncthreads();

    // ---- layer 3: 128 -> 64 ----
    {
        const unsigned char* hr = h2s + r * 132;
        #pragma unroll
        for (int j = 0; j < 4; j++) {
            int o = (g << 2) + j;
            int seg = SEG_W3 + o;
            int p0 = s_off[seg], p1 = s_off[seg + 1];
            int is = 0;
            for (int p = p0; p < p1; p += 4) {
                uint2 pk = *(const uint2*)(lst + p);
                unsigned e0 = pk.x & 0xffffu, e1 = pk.x >> 16;
                unsigned e2 = pk.y & 0xffffu, e3 = pk.y >> 16;
                int c0 = hr[e0 >> 2], c1 = hr[e1 >> 2];
                int c2 = hr[e2 >> 2], c3 = hr[e3 >> 2];
                is += csel(e0 & 3u, c0) + csel(e1 & 3u, c1)
                    + csel(e2 & 3u, c2) + csel(e3 & 3u, c3);
            }
            float y = fmaf((float)is * ACTS, s3, b3[o]);
            float qv = rintf(__fdiv_rn(y, ACTS));
            qv = fminf(fmaxf(qv, 0.0f), 3.0f);
            h3s[r * 68 + o] = (unsigned char)(int)qv;
        }
    }
    __syncthreads();

    // ---- output layer: 64 -> 128 ----
    {
        const unsigned char* hr = h3s + r * 68;
        #pragma unroll
        for (int j = 0; j < 8; j++) {
            int o = (g << 3) + j;
            int seg = SEG_WOUT + o;
            int p0 = s_off[seg], p1 = s_off[seg + 1];
            int is = 0;
            for (int p = p0; p < p1; p += 4) {
                uint2 pk = *(const uint2*)(lst + p);
                unsigned e0 = pk.x & 0xffffu, e1 = pk.x >> 16;
                unsigned e2 = pk.y & 0xffffu, e3 = pk.y >> 16;
                int c0 = hr[e0 >> 2], c1 = hr[e1 >> 2];
                int c2 = hr[e2 >> 2], c3 = hr[e3 >> 2];
                is += csel(e0 & 3u, c0) + csel(e1 & 3u, c1)
                    + csel(e2 & 3u, c2) + csel(e3 & 3u, c3);
            }
            outs[r * 132 + o] = ((float)is * ACTS) * s4;
        }
    }
    __syncthreads();

    // coalesced float4 store
    #pragma unroll
    for (int k = 0; k < 2; k++) {
        int q = tid + (k << 9);
        int rr = q >> 5, c4 = q & 31;
        float4 v = *(const float4*)&outs[rr * 132 + (c4 << 2)];
        *(float4*)&out[(size_t)(row0 + rr) * 128 + (c4 << 2)] = v;
    }
}

__global__ void __launch_bounds__(512, 2) mlp_main(
    const float* __restrict__ x,
    const float* __restrict__ b1a, const float* __restrict__ b1b,
    const float* __restrict__ b2,  const float* __restrict__ b3,
    float* __restrict__ out)
{
    extern __shared__ unsigned char smem[];
    float* xs0 = (float*)(smem);
    float* xs1 = (float*)(smem + 16896);
    unsigned char* h1s = smem + 33792;
    unsigned char* h2s = smem + 50304;
    unsigned char* h3s = smem + 54528;
    int*   s_off  = (int*)(smem + 56704);
    short* s_list = (short*)(smem + 66184);
    float* outs   = (float*)(smem);

    const int tid  = threadIdx.x;
    const int r    = tid & 31;
    const int g    = tid >> 5;
    const int row0 = blockIdx.x << 5;

    const float sc1a = __int_as_float(d_scale_bits[0]);
    const float sc1b = __int_as_float(d_scale_bits[1]);
    const float s2   = __int_as_float(d_scale_bits[2]);
    const float s3   = __int_as_float(d_scale_bits[3]);
    const float s4   = __int_as_float(d_scale_bits[4]);

    // kick off tile-0 loads first so staging overlaps DRAM latency
    {
        unsigned xs0a = (unsigned)__cvta_generic_to_shared(xs0);
        const float* xb = x + (size_t)row0 * 4096;
        #pragma unroll
        for (int k = 0; k < 8; k++) {
            int i = tid + (k << 9); int rr = i >> 7; int cc = i & 127;
            cp4(xs0a + (unsigned)((cc * 33 + rr) << 2), xb + (size_t)rr * 4096 + cc);
        }
        cp_commit();
    }

    for (int i = tid; i <= NSEG; i += 512) s_off[i] = d_off[i];
    const int total = d_off[NSEG];
    const bool use_sm = (total <= LIST_SM);
    if (use_sm)
        for (int i = tid; i < total; i += 512) s_list[i] = d_list[i];

    cp_wait0();
    __syncthreads();

    if (use_sm)
        mlp_body(s_list, s_off, xs0, xs1, h1s, h2s, h3s, outs,
                 x, b1a, b1b, b2, b3, out, row0, tid, r, g,
                 sc1a, sc1b, s2, s3, s4);
    else
        mlp_body(d_list, s_off, xs0, xs1, h1s, h2s, h3s, outs,
                 x, b1a, b1b, b2, b3, out, row0, tid, r, g,
                 sc1a, sc1b, s2, s3, s4);
}

// ---------------- launch ----------------
extern "C" void kernel_launch(void* const* d_in, const int* in_sizes, int n_in,
                              void* d_out, int out_size)
{
    const float* x    = (const float*)d_in[0];
    const float* W1a  = (const float*)d_in[1];
    const float* b1a  = (const float*)d_in[2];
    const float* W1b  = (const float*)d_in[3];
    const float* b1b  = (const float*)d_in[4];
    const float* W2   = (const float*)d_in[5];
    const float* b2   = (const float*)d_in[6];
    const float* W3   = (const float*)d_in[7];
    const float* b3   = (const float*)d_in[8];
    const float* Wout = (const float*)d_in[9];
    float* out = (float*)d_out;

    prep_init<<<1, 32>>>();
    prep_scale<<<160, 256>>>(W1a, W1b, W2, W3, Wout);
    prep_count<<<NSEG / 8, 256>>>(W1a, W1b, W2, W3, Wout);
    prep_scan<<<1, 1024>>>();
    prep_fill<<<NSEG / 8, 256>>>(W1a, W1b, W2, W3, Wout);

    cudaFuncSetAttribute(mlp_main, cudaFuncAttributeMaxDynamicSharedMemorySize, SMEM_BYTES);
    mlp_main<<<1024, 512, SMEM_BYTES>>>(x, b1a, b1b, b2, b3, out);
}

// round 4
// speedup vs baseline: 1.3842x; 1.3842x over previous
#include <cuda_runtime.h>
#include <cstdint>
#include <cstddef>

// ---------------- constants ----------------
// segment layout:
//  L1  : seg = ((m*4 + q) << 7) + o   m in {0,1}, q in 0..3 (256-col chunk), o in 0..127  -> 1024 segs, len 256
//  W2  : 1024 + o   (128 segs, len 512)
//  W3  : 1152 + o   ( 64 segs, len 128)
//  Wout: 1216 + o   (128 segs, len  64)
#define NSEG       1344
#define SEG_W2     1024
#define SEG_W3     1152
#define SEG_WOUT   1216
#define LIST_MAX   360448
#define LIST_CAP   9216          // smem staging capacity (entries)
#define ACTS       1.3333333730697632f

#define ROWS       64            // batch rows per block
#define THREADS    1024
#define GRID       512           // 32768/64

// ---------------- device scratch ----------------
__device__ int   d_scale_bits[5];      // zero-init; atomicMax idempotent across replays
__device__ int   d_cnt[NSEG];
__device__ int   d_off[NSEG + 1];
__device__ __align__(16) short d_list[LIST_MAX];

// ---------------- prep: per-tensor max|w| ----------------
__global__ void prep_scale(const float* __restrict__ W1a, const float* __restrict__ W1b,
                           const float* __restrict__ W2,  const float* __restrict__ W3,
                           const float* __restrict__ Wout)
{
    __shared__ float red[8];
    int m = blockIdx.x >> 5;
    int part = blockIdx.x & 31;
    const float* W; int n;
    switch (m) {
        case 0: W = W1a;  n = 131072; break;
        case 1: W = W1b;  n = 131072; break;
        case 2: W = W2;   n = 65536;  break;
        case 3: W = W3;   n = 8192;   break;
        default: W = Wout; n = 8192;  break;
    }
    int chunk = n >> 5;
    int lo = part * chunk;
    float mx = 0.0f;
    for (int i = lo + threadIdx.x; i < lo + chunk; i += 256)
        mx = fmaxf(mx, fabsf(W[i]));
    #pragma unroll
    for (int o = 16; o; o >>= 1) mx = fmaxf(mx, __shfl_xor_sync(0xffffffffu, mx, o));
    if ((threadIdx.x & 31) == 0) red[threadIdx.x >> 5] = mx;
    __syncthreads();
    if (threadIdx.x < 32) {
        float v = (threadIdx.x < 8) ? red[threadIdx.x] : 0.0f;
        #pragma unroll
        for (int o = 4; o; o >>= 1) v = fmaxf(v, __shfl_xor_sync(0xffffffffu, v, o));
        if (threadIdx.x == 0) atomicMax(&d_scale_bits[m], __float_as_int(v));
    }
}

// ---------------- segment decode ----------------
struct SegInfo { const float* rowp; int len; float s; };

__device__ __forceinline__ SegInfo seg_decode(int seg,
    const float* W1a, const float* W1b, const float* W2,
    const float* W3, const float* Wout)
{
    SegInfo r;
    if (seg < SEG_W2) {
        int m = seg >> 9, rem = seg & 511;
        int q = rem >> 7, o = rem & 127;
        r.rowp = (m ? W1b : W1a) + o * 1024 + q * 256;
        r.len = 256; r.s = __int_as_float(d_scale_bits[m]);
    } else if (seg < SEG_W3) {
        r.rowp = W2 + (seg - SEG_W2) * 512;
        r.len = 512; r.s = __int_as_float(d_scale_bits[2]);
    } else if (seg < SEG_WOUT) {
        r.rowp = W3 + (seg - SEG_W3) * 128;
        r.len = 128; r.s = __int_as_float(d_scale_bits[3]);
    } else {
        r.rowp = Wout + (seg - SEG_WOUT) * 64;
        r.len = 64; r.s = __int_as_float(d_scale_bits[4]);
    }
    return r;
}

// ---------------- prep: count nnz per segment (pad to 4) ----------------
__global__ void prep_count(const float* __restrict__ W1a, const float* __restrict__ W1b,
                           const float* __restrict__ W2,  const float* __restrict__ W3,
                           const float* __restrict__ Wout)
{
    int lane = threadIdx.x & 31;
    int seg = blockIdx.x * 8 + (threadIdx.x >> 5);
    if (seg >= NSEG) return;
    SegInfo si = seg_decode(seg, W1a, W1b, W2, W3, Wout);
    int cnt = 0;
    for (int j0 = 0; j0 < si.len; j0 += 32) {
        float w = si.rowp[j0 + lane];
        float q = rintf(__fdiv_rn(w, si.s));
        unsigned bal = __ballot_sync(0xffffffffu, q != 0.0f);
        cnt += __popc(bal);
    }
    if (lane == 0) d_cnt[seg] = (cnt + 3) & ~3;
}

// ---------------- prep: exclusive scan (1 block, 512 thr x 3) ----------------
__global__ void prep_scan() {
    __shared__ int warpsum[16];
    int tid = threadIdx.x;
    int lane = tid & 31, w = tid >> 5;
    int base = tid * 3;
    int v[3]; int s = 0;
    #pragma unroll
    for (int k = 0; k < 3; k++) {
        int idx = base + k;
        int c = (idx < NSEG) ? d_cnt[idx] : 0;
        v[k] = s; s += c;
    }
    int incl = s;
    #pragma unroll
    for (int o = 1; o < 32; o <<= 1) {
        int t = __shfl_up_sync(0xffffffffu, incl, o);
        if (lane >= o) incl += t;
    }
    if (lane == 31) warpsum[w] = incl;
    __syncthreads();
    if (w == 0 && lane < 16) {
        int ws = warpsum[lane];
        #pragma unroll
        for (int o = 1; o < 16; o <<= 1) {
            int t = __shfl_up_sync(0xffffu, ws, o);
            if (lane >= o) ws += t;
        }
        warpsum[lane] = ws;
    }
    __syncthreads();
    int excl = incl - s + (w ? warpsum[w - 1] : 0);
    #pragma unroll
    for (int k = 0; k < 3; k++) {
        int idx = base + k;
        if (idx <= NSEG) d_off[idx] = excl + v[k];
    }
}

// ---------------- prep: fill padded lists ----------------
// entry = (local_idx << 2) | cls ; cls: 1 = +s, 2 = -s, 0 = pad
__global__ void prep_fill(const float* __restrict__ W1a, const float* __restrict__ W1b,
                          const float* __restrict__ W2,  const float* __restrict__ W3,
                          const float* __restrict__ Wout)
{
    int lane = threadIdx.x & 31;
    int seg = blockIdx.x * 8 + (threadIdx.x >> 5);
    if (seg >= NSEG) return;
    SegInfo si = seg_decode(seg, W1a, W1b, W2, W3, Wout);
    int base = d_off[seg];
    for (int j0 = 0; j0 < si.len; j0 += 32) {
        float w = si.rowp[j0 + lane];
        float q = rintf(__fdiv_rn(w, si.s));
        bool nz = (q != 0.0f);
        unsigned bal = __ballot_sync(0xffffffffu, nz);
        if (nz) {
            int pos = base + __popc(bal & ((1u << lane) - 1u));
            int e = ((j0 + lane) << 2) | (q > 0.0f ? 1 : 2);
            d_list[pos] = (short)e;
        }
        base += __popc(bal);
    }
    int end = d_off[seg + 1];
    for (int p = base + lane; p < end; p += 32) d_list[p] = 0;
}

// ---------------- main kernel ----------------
// smem (bytes):
//  XS0  @ 0       : 256*66*4 = 67584   (x tile: [col][row], stride 66 words)
//  XS1  @ 67584   : 67584
//  H1   @ 135168  : 512*66   = 33792   (codes: [idx][row], stride 66 bytes)
//  H2   @ 168960  : 128*66   =  8448
//  H3   @ 177408  :  64*66   =  4224
//  OFF  @ 181632  : 1345*4   =  5380 (+4 pad)
//  LIST @ 187016  : 9216*2   = 18432
//  total 205448 ; OUTS (64*132*4 = 33792) aliases XS0
#define SMEM_BYTES 205448

__device__ __forceinline__ float wsel(unsigned c, float sc) {
    float w = (c == 1u) ? sc : 0.0f;
    return (c == 2u) ? -sc : w;
}
__device__ __forceinline__ int csel(unsigned c, int v) {
    int r = (c == 1u) ? v : 0;
    return (c == 2u) ? -v : r;
}
__device__ __forceinline__ float quant_relu_q(float y) {
    float qv = rintf(__fdiv_rn(y, ACTS));
    return fminf(fmaxf(qv, 0.0f), 3.0f);
}

template<bool USE_SM>
__device__ __forceinline__ void mlp_body(
    unsigned char* smem,
    const float* __restrict__ x,
    const float* __restrict__ b1a, const float* __restrict__ b1b,
    const float* __restrict__ b2,  const float* __restrict__ b3,
    float* __restrict__ out, int row0)
{
    float* xs0 = (float*)(smem);
    float* xs1 = (float*)(smem + 67584);
    unsigned char* h1s = smem + 135168;
    unsigned char* h2s = smem + 168960;
    unsigned char* h3s = smem + 177408;
    int*   s_off  = (int*)(smem + 181632);
    const short* lst = USE_SM ? (const short*)(smem + 187016) : (const short*)d_list;
    float* outs = (float*)(smem);      // alias XS0

    const int tid = threadIdx.x;
    const int lane = tid & 31;
    const int g = tid >> 5;            // warp id 0..31
    const int r2 = lane << 1;          // two rows per lane: 2*lane, 2*lane+1

    const float sc1a = __int_as_float(d_scale_bits[0]);
    const float sc1b = __int_as_float(d_scale_bits[1]);
    const float s2   = __int_as_float(d_scale_bits[2]);
    const float s3   = __int_as_float(d_scale_bits[3]);
    const float s4   = __int_as_float(d_scale_bits[4]);

    float4 pf[4];

    // preload tile 0
    {
        #pragma unroll
        for (int k = 0; k < 4; k++) {
            int i4 = tid + (k << 10);
            int rr = i4 >> 6, cb = (i4 & 63) << 2;
            pf[k] = __ldcs((const float4*)(x + (size_t)(row0 + rr) * 4096 + cb));
        }
        #pragma unroll
        for (int k = 0; k < 4; k++) {
            int i4 = tid + (k << 10);
            int rr = i4 >> 6, cb = (i4 & 63) << 2;
            xs0[(cb + 0) * 66 + rr] = pf[k].x;
            xs0[(cb + 1) * 66 + rr] = pf[k].y;
            xs0[(cb + 2) * 66 + rr] = pf[k].z;
            xs0[(cb + 3) * 66 + rr] = pf[k].w;
        }
    }
    __syncthreads();
    // issue loads for tile 1
    {
        #pragma unroll
        for (int k = 0; k < 4; k++) {
            int i4 = tid + (k << 10);
            int rr = i4 >> 6, cb = (i4 & 63) << 2;
            pf[k] = __ldcs((const float4*)(x + (size_t)(row0 + rr) * 4096 + 256 + cb));
        }
    }

    float acc0[4], acc1[4];
    #pragma unroll
    for (int j = 0; j < 4; j++) { acc0[j] = 0.0f; acc1[j] = 0.0f; }

    // ---- layer 1: 16 tiles of [64 rows x 256 cols] ----
    for (int t = 0; t < 16; ++t) {
        const int branch = t >> 2, q = t & 3, m = branch & 1;
        const float* cur = (t & 1) ? xs1 : xs0;
        const float  sc  = m ? sc1b : sc1a;

        #pragma unroll
        for (int j = 0; j < 4; j++) {
            int o = (g << 2) + j;
            int seg = ((m * 4 + q) << 7) + o;
            int p0 = s_off[seg], p1 = s_off[seg + 1];
            float a0 = acc0[j], a1 = acc1[j];
            for (int p = p0; p < p1; p += 4) {
                uint2 pk = *(const uint2*)(lst + p);
                unsigned e0 = pk.x & 0xffffu, e1 = pk.x >> 16;
                unsigned e2 = pk.y & 0xffffu, e3 = pk.y >> 16;
                float2 v0 = *(const float2*)(cur + (e0 >> 2) * 66 + r2);
                float2 v1 = *(const float2*)(cur + (e1 >> 2) * 66 + r2);
                float2 v2 = *(const float2*)(cur + (e2 >> 2) * 66 + r2);
                float2 v3 = *(const float2*)(cur + (e3 >> 2) * 66 + r2);
                float w0 = wsel(e0 & 3u, sc), w1 = wsel(e1 & 3u, sc);
                float w2 = wsel(e2 & 3u, sc), w3 = wsel(e3 & 3u, sc);
                a0 = fmaf(w0, v0.x, a0); a1 = fmaf(w0, v0.y, a1);
                a0 = fmaf(w1, v1.x, a0); a1 = fmaf(w1, v1.y, a1);
                a0 = fmaf(w2, v2.x, a0); a1 = fmaf(w2, v2.y, a1);
                a0 = fmaf(w3, v3.x, a0); a1 = fmaf(w3, v3.y, a1);
            }
            acc0[j] = a0; acc1[j] = a1;
        }

        if (q == 3) {   // branch complete -> quantize + store codes (2 rows packed u16)
            const float* bb = m ? b1b : b1a;
            #pragma unroll
            for (int j = 0; j < 4; j++) {
                int o = (g << 2) + j;
                float bv = bb[o];
                unsigned c0 = (unsigned)(int)quant_relu_q(acc0[j] + bv);
                unsigned c1 = (unsigned)(int)quant_relu_q(acc1[j] + bv);
                *(unsigned short*)(h1s + (branch * 128 + o) * 66 + r2) =
                    (unsigned short)(c0 | (c1 << 8));
                acc0[j] = 0.0f; acc1[j] = 0.0f;
            }
        }

        if (t + 1 < 16) {
            float* nxt = (t & 1) ? xs0 : xs1;
            #pragma unroll
            for (int k = 0; k < 4; k++) {
                int i4 = tid + (k << 10);
                int rr = i4 >> 6, cb = (i4 & 63) << 2;
                nxt[(cb + 0) * 66 + rr] = pf[k].x;
                nxt[(cb + 1) * 66 + rr] = pf[k].y;
                nxt[(cb + 2) * 66 + rr] = pf[k].z;
                nxt[(cb + 3) * 66 + rr] = pf[k].w;
            }
            __syncthreads();
            if (t + 2 < 16) {
                int nb = (t + 2) >> 2, nq = (t + 2) & 3;
                #pragma unroll
                for (int k = 0; k < 4; k++) {
                    int i4 = tid + (k << 10);
                    int rr = i4 >> 6, cb = (i4 & 63) << 2;
                    pf[k] = __ldcs((const float4*)(x + (size_t)(row0 + rr) * 4096
                                                   + nb * 1024 + nq * 256 + cb));
                }
            }
        }
    }
    __syncthreads();

    // ---- layer 2: 512 -> 128 (4 outputs/warp) ----
    #pragma unroll
    for (int j = 0; j < 4; j++) {
        int o = (g << 2) + j;
        int seg = SEG_W2 + o;
        int p0 = s_off[seg], p1 = s_off[seg + 1];
        int is0 = 0, is1 = 0;
        for (int p = p0; p < p1; p += 4) {
            uint2 pk = *(const uint2*)(lst + p);
            unsigned e0 = pk.x & 0xffffu, e1 = pk.x >> 16;
            unsigned e2 = pk.y & 0xffffu, e3 = pk.y >> 16;
            unsigned c0 = *(const unsigned short*)(h1s + (e0 >> 2) * 66 + r2);
            unsigned c1 = *(const unsigned short*)(h1s + (e1 >> 2) * 66 + r2);
            unsigned c2 = *(const unsigned short*)(h1s + (e2 >> 2) * 66 + r2);
            unsigned c3 = *(const unsigned short*)(h1s + (e3 >> 2) * 66 + r2);
            is0 += csel(e0 & 3u, (int)(c0 & 0xffu)) + csel(e1 & 3u, (int)(c1 & 0xffu))
                 + csel(e2 & 3u, (int)(c2 & 0xffu)) + csel(e3 & 3u, (int)(c3 & 0xffu));
            is1 += csel(e0 & 3u, (int)(c0 >> 8)) + csel(e1 & 3u, (int)(c1 >> 8))
                 + csel(e2 & 3u, (int)(c2 >> 8)) + csel(e3 & 3u, (int)(c3 >> 8));
        }
        float bv = b2[o];
        unsigned q0 = (unsigned)(int)quant_relu_q(fmaf((float)is0 * ACTS, s2, bv));
        unsigned q1 = (unsigned)(int)quant_relu_q(fmaf((float)is1 * ACTS, s2, bv));
        *(unsigned short*)(h2s + o * 66 + r2) = (unsigned short)(q0 | (q1 << 8));
    }
    __syncthreads();

    // ---- layer 3: 128 -> 64 (2 outputs/warp) ----
    #pragma unroll
    for (int j = 0; j < 2; j++) {
        int o = (g << 1) + j;
        int seg = SEG_W3 + o;
        int p0 = s_off[seg], p1 = s_off[seg + 1];
        int is0 = 0, is1 = 0;
        for (int p = p0; p < p1; p += 4) {
            uint2 pk = *(const uint2*)(lst + p);
            unsigned e0 = pk.x & 0xffffu, e1 = pk.x >> 16;
            unsigned e2 = pk.y & 0xffffu, e3 = pk.y >> 16;
            unsigned c0 = *(const unsigned short*)(h2s + (e0 >> 2) * 66 + r2);
            unsigned c1 = *(const unsigned short*)(h2s + (e1 >> 2) * 66 + r2);
            unsigned c2 = *(const unsigned short*)(h2s + (e2 >> 2) * 66 + r2);
            unsigned c3 = *(const unsigned short*)(h2s + (e3 >> 2) * 66 + r2);
            is0 += csel(e0 & 3u, (int)(c0 & 0xffu)) + csel(e1 & 3u, (int)(c1 & 0xffu))
                 + csel(e2 & 3u, (int)(c2 & 0xffu)) + csel(e3 & 3u, (int)(c3 & 0xffu));
            is1 += csel(e0 & 3u, (int)(c0 >> 8)) + csel(e1 & 3u, (int)(c1 >> 8))
                 + csel(e2 & 3u, (int)(c2 >> 8)) + csel(e3 & 3u, (int)(c3 >> 8));
        }
        float bv = b3[o];
        unsigned q0 = (unsigned)(int)quant_relu_q(fmaf((float)is0 * ACTS, s3, bv));
        unsigned q1 = (unsigned)(int)quant_relu_q(fmaf((float)is1 * ACTS, s3, bv));
        *(unsigned short*)(h3s + o * 66 + r2) = (unsigned short)(q0 | (q1 << 8));
    }
    __syncthreads();

    // ---- output layer: 64 -> 128 (4 outputs/warp), no bias ----
    #pragma unroll
    for (int j = 0; j < 4; j++) {
        int o = (g << 2) + j;
        int seg = SEG_WOUT + o;
        int p0 = s_off[seg], p1 = s_off[seg + 1];
        int is0 = 0, is1 = 0;
        for (int p = p0; p < p1; p += 4) {
            uint2 pk = *(const uint2*)(lst + p);
            unsigned e0 = pk.x & 0xffffu, e1 = pk.x >> 16;
            unsigned e2 = pk.y & 0xffffu, e3 = pk.y >> 16;
            unsigned c0 = *(const unsigned short*)(h3s + (e0 >> 2) * 66 + r2);
            unsigned c1 = *(const unsigned short*)(h3s + (e1 >> 2) * 66 + r2);
            unsigned c2 = *(const unsigned short*)(h3s + (e2 >> 2) * 66 + r2);
            unsigned c3 = *(const unsigned short*)(h3s + (e3 >> 2) * 66 + r2);
            is0 += csel(e0 & 3u, (int)(c0 & 0xffu)) + csel(e1 & 3u, (int)(c1 & 0xffu))
                 + csel(e2 & 3u, (int)(c2 & 0xffu)) + csel(e3 & 3u, (int)(c3 & 0xffu));
            is1 += csel(e0 & 3u, (int)(c0 >> 8)) + csel(e1 & 3u, (int)(c1 >> 8))
                 + csel(e2 & 3u, (int)(c2 >> 8)) + csel(e3 & 3u, (int)(c3 >> 8));
        }
        outs[(r2 + 0) * 132 + o] = ((float)is0 * ACTS) * s4;
        outs[(r2 + 1) * 132 + o] = ((float)is1 * ACTS) * s4;
    }
    __syncthreads();

    // coalesced float4 store: 64 rows x 128 cols
    #pragma unroll
    for (int k = 0; k < 2; k++) {
        int qi = tid + (k << 10);
        int rr = qi >> 5, c4 = qi & 31;
        float4 v = *(const float4*)&outs[rr * 132 + (c4 << 2)];
        *(float4*)&out[(size_t)(row0 + rr) * 128 + (c4 << 2)] = v;
    }
}

__global__ void __launch_bounds__(THREADS, 1) mlp_main(
    const float* __restrict__ x,
    const float* __restrict__ b1a, const float* __restrict__ b1b,
    const float* __restrict__ b2,  const float* __restrict__ b3,
    float* __restrict__ out)
{
    extern __shared__ unsigned char smem[];
    int*   s_off  = (int*)(smem + 181632);
    short* s_list = (short*)(smem + 187016);

    const int tid = threadIdx.x;
    const int row0 = blockIdx.x << 6;

    for (int i = tid; i <= NSEG; i += THREADS) s_off[i] = d_off[i];
    const int total = d_off[NSEG];
    const bool use_sm = (total <= LIST_CAP);
    if (use_sm)
        for (int i = tid; i < total; i += THREADS) s_list[i] = d_list[i];
    __syncthreads();

    if (use_sm)
        mlp_body<true>(smem, x, b1a, b1b, b2, b3, out, row0);
    else
        mlp_body<false>(smem, x, b1a, b1b, b2, b3, out, row0);
}

// ---------------- launch ----------------
extern "C" void kernel_launch(void* const* d_in, const int* in_sizes, int n_in,
                              void* d_out, int out_size)
{
    const float* x    = (const float*)d_in[0];
    const float* W1a  = (const float*)d_in[1];
    const float* b1a  = (const float*)d_in[2];
    const float* W1b  = (const float*)d_in[3];
    const float* b1b  = (const float*)d_in[4];
    const float* W2   = (const float*)d_in[5];
    const float* b2   = (const float*)d_in[6];
    const float* W3   = (const float*)d_in[7];
    const float* b3   = (const float*)d_in[8];
    const float* Wout = (const float*)d_in[9];
    float* out = (float*)d_out;

    prep_scale<<<160, 256>>>(W1a, W1b, W2, W3, Wout);
    prep_count<<<NSEG / 8, 256>>>(W1a, W1b, W2, W3, Wout);
    prep_scan<<<1, 512>>>();
    prep_fill<<<NSEG / 8, 256>>>(W1a, W1b, W2, W3, Wout);

    cudaFuncSetAttribute(mlp_main, cudaFuncAttributeMaxDynamicSharedMemorySize, SMEM_BYTES);
    mlp_main<<<GRID, THREADS, SMEM_BYTES>>>(x, b1a, b1b, b2, b3, out);
}

// round 5
// speedup vs baseline: 1.5521x; 1.1213x over previous
#include <cuda_runtime.h>
#include <cstdint>
#include <cstddef>

// ---------------- constants ----------------
// segment layout:
//  L1  : seg = ((m*4 + q) << 7) + o   m in {0,1}, q in 0..3 (256-col chunk), o in 0..127  -> 1024 segs, len 256
//  W2  : 1024 + o   (128 segs, len 512)
//  W3  : 1152 + o   ( 64 segs, len 128)
//  Wout: 1216 + o   (128 segs, len  64)
#define NSEG       1344
#define SEG_W2     1024
#define SEG_W3     1152
#define SEG_WOUT   1216
#define LIST_MAX   360448
#define LIST_CAP   16384         // smem staging capacity (entries) — actual ~13.5K
#define ACTS       1.3333333730697632f

#define ROWS       64            // batch rows per block
#define THREADS    1024
#define GRID       512           // 32768/64

// ---------------- device scratch ----------------
__device__ int   d_scale_bits[5];      // zero-init; atomicMax idempotent across replays
__device__ int   d_cnt[NSEG];
__device__ int   d_off[NSEG + 1];
__device__ __align__(16) short d_list[LIST_MAX];

// ---------------- prep 1: per-tensor max|w| ----------------
__global__ void prep_scale(const float* __restrict__ W1a, const float* __restrict__ W1b,
                           const float* __restrict__ W2,  const float* __restrict__ W3,
                           const float* __restrict__ Wout)
{
    __shared__ float red[8];
    int m = blockIdx.x >> 5;
    int part = blockIdx.x & 31;
    const float* W; int n;
    switch (m) {
        case 0: W = W1a;  n = 131072; break;
        case 1: W = W1b;  n = 131072; break;
        case 2: W = W2;   n = 65536;  break;
        case 3: W = W3;   n = 8192;   break;
        default: W = Wout; n = 8192;  break;
    }
    int chunk = n >> 5;
    int lo = part * chunk;
    float mx = 0.0f;
    for (int i = lo + threadIdx.x; i < lo + chunk; i += 256)
        mx = fmaxf(mx, fabsf(W[i]));
    #pragma unroll
    for (int o = 16; o; o >>= 1) mx = fmaxf(mx, __shfl_xor_sync(0xffffffffu, mx, o));
    if ((threadIdx.x & 31) == 0) red[threadIdx.x >> 5] = mx;
    __syncthreads();
    if (threadIdx.x < 32) {
        float v = (threadIdx.x < 8) ? red[threadIdx.x] : 0.0f;
        #pragma unroll
        for (int o = 4; o; o >>= 1) v = fmaxf(v, __shfl_xor_sync(0xffffffffu, v, o));
        if (threadIdx.x == 0) atomicMax(&d_scale_bits[m], __float_as_int(v));
    }
}

// ---------------- segment decode ----------------
struct SegInfo { const float* rowp; int len; float s; };

__device__ __forceinline__ SegInfo seg_decode(int seg,
    const float* W1a, const float* W1b, const float* W2,
    const float* W3, const float* Wout)
{
    SegInfo r;
    if (seg < SEG_W2) {
        int m = seg >> 9, rem = seg & 511;
        int q = rem >> 7, o = rem & 127;
        r.rowp = (m ? W1b : W1a) + o * 1024 + q * 256;
        r.len = 256; r.s = __int_as_float(d_scale_bits[m]);
    } else if (seg < SEG_W3) {
        r.rowp = W2 + (seg - SEG_W2) * 512;
        r.len = 512; r.s = __int_as_float(d_scale_bits[2]);
    } else if (seg < SEG_WOUT) {
        r.rowp = W3 + (seg - SEG_W3) * 128;
        r.len = 128; r.s = __int_as_float(d_scale_bits[3]);
    } else {
        r.rowp = Wout + (seg - SEG_WOUT) * 64;
        r.len = 64; r.s = __int_as_float(d_scale_bits[4]);
    }
    return r;
}

// ---------------- prep 2: count nnz per segment (pad to 4) ----------------
__global__ void prep_count(const float* __restrict__ W1a, const float* __restrict__ W1b,
                           const float* __restrict__ W2,  const float* __restrict__ W3,
                           const float* __restrict__ Wout)
{
    int lane = threadIdx.x & 31;
    int seg = blockIdx.x * 8 + (threadIdx.x >> 5);
    if (seg >= NSEG) return;
    SegInfo si = seg_decode(seg, W1a, W1b, W2, W3, Wout);
    int cnt = 0;
    for (int j0 = 0; j0 < si.len; j0 += 32) {
        float w = si.rowp[j0 + lane];
        float q = rintf(__fdiv_rn(w, si.s));
        unsigned bal = __ballot_sync(0xffffffffu, q != 0.0f);
        cnt += __popc(bal);
    }
    if (lane == 0) d_cnt[seg] = (cnt + 3) & ~3;
}

// ---------------- prep 3: scan (redundant per block) + fill ----------------
// entry = (local_idx << 2) | cls ; cls: 1 = +s, 2 = -s, 0 = pad
__global__ void prep_scanfill(const float* __restrict__ W1a, const float* __restrict__ W1b,
                              const float* __restrict__ W2,  const float* __restrict__ W3,
                              const float* __restrict__ Wout)
{
    __shared__ int s_off[NSEG + 1];
    __shared__ int warpsum[8];
    int tid = threadIdx.x;
    int lane = tid & 31, w = tid >> 5;

    // local exclusive scan of d_cnt (256 threads x 6 elems = 1536 >= 1345)
    {
        int base = tid * 6;
        int v[6]; int s = 0;
        #pragma unroll
        for (int k = 0; k < 6; k++) {
            int idx = base + k;
            int c = (idx < NSEG) ? d_cnt[idx] : 0;
            v[k] = s; s += c;
        }
        int incl = s;
        #pragma unroll
        for (int o = 1; o < 32; o <<= 1) {
            int t = __shfl_up_sync(0xffffffffu, incl, o);
            if (lane >= o) incl += t;
        }
        if (lane == 31) warpsum[w] = incl;
        __syncthreads();
        if (w == 0 && lane < 8) {
            int ws = warpsum[lane];
            #pragma unroll
            for (int o = 1; o < 8; o <<= 1) {
                int t = __shfl_up_sync(0xffu, ws, o);
                if (lane >= o) ws += t;
            }
            warpsum[lane] = ws;
        }
        __syncthreads();
        int excl = incl - s + (w ? warpsum[w - 1] : 0);
        #pragma unroll
        for (int k = 0; k < 6; k++) {
            int idx = base + k;
            if (idx <= NSEG) s_off[idx] = excl + v[k];
        }
        __syncthreads();
    }

    // block 0 publishes offsets for mlp_main
    if (blockIdx.x == 0)
        for (int i = tid; i <= NSEG; i += 256) d_off[i] = s_off[i];

    // fill (grid-stride over segments, one warp per segment)
    for (int seg = blockIdx.x * 8 + w; seg < NSEG; seg += gridDim.x * 8) {
        SegInfo si = seg_decode(seg, W1a, W1b, W2, W3, Wout);
        int base = s_off[seg];
        for (int j0 = 0; j0 < si.len; j0 += 32) {
            float wv = si.rowp[j0 + lane];
            float q = rintf(__fdiv_rn(wv, si.s));
            bool nz = (q != 0.0f);
            unsigned bal = __ballot_sync(0xffffffffu, nz);
            if (nz) {
                int pos = base + __popc(bal & ((1u << lane) - 1u));
                int e = ((j0 + lane) << 2) | (q > 0.0f ? 1 : 2);
                d_list[pos] = (short)e;
            }
            base += __popc(bal);
        }
        int end = s_off[seg + 1];
        for (int p = base + lane; p < end; p += 32) d_list[p] = 0;
    }
}

// ---------------- main kernel ----------------
// smem (bytes):
//  XS0  @ 0       : 256*66*4 = 67584   (x tile: [col][row], word stride 66)
//  XS1  @ 67584   : 67584
//  H1   @ 135168  : 512*66   = 33792   (codes: [idx][row], byte stride 66)
//  H2   @ 168960  : 128*66   =  8448
//  H3   @ 177408  :  64*66   =  4224
//  OFF  @ 181632  : 1345*4   =  5380 (+4 pad)
//  LIST @ 187016  : 16384*2  = 32768
//  total 219784 ; OUTS (64*132*4 = 33792) aliases XS0
#define SMEM_BYTES 219784

__device__ __forceinline__ float wsel(unsigned c, float sc) {
    float w = (c == 1u) ? sc : 0.0f;
    return (c == 2u) ? -sc : w;
}
__device__ __forceinline__ int csel(unsigned c, int v) {
    int r = (c == 1u) ? v : 0;
    return (c == 2u) ? -v : r;
}
__device__ __forceinline__ float quant_relu_q(float y) {
    float qv = rintf(__fdiv_rn(y, ACTS));
    return fminf(fmaxf(qv, 0.0f), 3.0f);
}

template<bool USE_SM>
__device__ __forceinline__ void mlp_body(
    unsigned char* smem,
    const float* __restrict__ x,
    const float* __restrict__ b1a, const float* __restrict__ b1b,
    const float* __restrict__ b2,  const float* __restrict__ b3,
    float* __restrict__ out, int row0)
{
    float* xs0 = (float*)(smem);
    float* xs1 = (float*)(smem + 67584);
    unsigned char* h1s = smem + 135168;
    unsigned char* h2s = smem + 168960;
    unsigned char* h3s = smem + 177408;
    int*   s_off  = (int*)(smem + 181632);
    const short* lst = USE_SM ? (const short*)(smem + 187016) : (const short*)d_list;
    float* outs = (float*)(smem);      // alias XS0

    const int tid = threadIdx.x;
    const int lane = tid & 31;
    const int g = tid >> 5;            // warp id 0..31
    const int r2 = lane << 1;          // two rows per lane for gather

    // staging role: lanes 0-15 -> row 2g, lanes 16-31 -> row 2g+1 (conflict-free banks)
    const int halfrow = lane >> 4;
    const int cl = lane & 15;
    const int srow = (g << 1) + halfrow;
    const float* xrow = x + (size_t)(row0 + srow) * 4096;

    const float sc1a = __int_as_float(d_scale_bits[0]);
    const float sc1b = __int_as_float(d_scale_bits[1]);
    const float s2   = __int_as_float(d_scale_bits[2]);
    const float s3   = __int_as_float(d_scale_bits[3]);
    const float s4   = __int_as_float(d_scale_bits[4]);

    float pf[16];

    // preload tile 0 (tile t covers cols t*256 .. t*256+255)
    #pragma unroll
    for (int k = 0; k < 16; k++) pf[k] = __ldcs(xrow + cl + (k << 4));
    #pragma unroll
    for (int k = 0; k < 16; k++) xs0[(cl + (k << 4)) * 66 + srow] = pf[k];
    __syncthreads();
    // issue loads for tile 1
    #pragma unroll
    for (int k = 0; k < 16; k++) pf[k] = __ldcs(xrow + 256 + cl + (k << 4));

    float acc0[4], acc1[4];
    #pragma unroll
    for (int j = 0; j < 4; j++) { acc0[j] = 0.0f; acc1[j] = 0.0f; }

    // ---- layer 1: 16 tiles of [64 rows x 256 cols] ----
    for (int t = 0; t < 16; ++t) {
        const int branch = t >> 2, q = t & 3, m = branch & 1;
        const float* cur = (t & 1) ? xs1 : xs0;
        const float  sc  = m ? sc1b : sc1a;

        #pragma unroll
        for (int j = 0; j < 4; j++) {
            int o = (g << 2) + j;
            int seg = ((m * 4 + q) << 7) + o;
            int p0 = s_off[seg], p1 = s_off[seg + 1];
            float a0 = acc0[j], a1 = acc1[j];
            for (int p = p0; p < p1; p += 4) {
                uint2 pk = *(const uint2*)(lst + p);
                unsigned e0 = pk.x & 0xffffu, e1 = pk.x >> 16;
                unsigned e2 = pk.y & 0xffffu, e3 = pk.y >> 16;
                float2 v0 = *(const float2*)(cur + (e0 >> 2) * 66 + r2);
                float2 v1 = *(const float2*)(cur + (e1 >> 2) * 66 + r2);
                float2 v2 = *(const float2*)(cur + (e2 >> 2) * 66 + r2);
                float2 v3 = *(const float2*)(cur + (e3 >> 2) * 66 + r2);
                float w0 = wsel(e0 & 3u, sc), w1 = wsel(e1 & 3u, sc);
                float w2 = wsel(e2 & 3u, sc), w3 = wsel(e3 & 3u, sc);
                a0 = fmaf(w0, v0.x, a0); a1 = fmaf(w0, v0.y, a1);
                a0 = fmaf(w1, v1.x, a0); a1 = fmaf(w1, v1.y, a1);
                a0 = fmaf(w2, v2.x, a0); a1 = fmaf(w2, v2.y, a1);
                a0 = fmaf(w3, v3.x, a0); a1 = fmaf(w3, v3.y, a1);
            }
            acc0[j] = a0; acc1[j] = a1;
        }

        if (q == 3) {   // branch complete -> quantize + store codes (2 rows packed u16)
            const float* bb = m ? b1b : b1a;
            #pragma unroll
            for (int j = 0; j < 4; j++) {
                int o = (g << 2) + j;
                float bv = bb[o];
                unsigned c0 = (unsigned)(int)quant_relu_q(acc0[j] + bv);
                unsigned c1 = (unsigned)(int)quant_relu_q(acc1[j] + bv);
                *(unsigned short*)(h1s + (branch * 128 + o) * 66 + r2) =
                    (unsigned short)(c0 | (c1 << 8));
                acc0[j] = 0.0f; acc1[j] = 0.0f;
            }
        }

        if (t + 1 < 16) {
            float* nxt = (t & 1) ? xs0 : xs1;
            #pragma unroll
            for (int k = 0; k < 16; k++)
                nxt[(cl + (k << 4)) * 66 + srow] = pf[k];
            __syncthreads();
            if (t + 2 < 16) {
                const float* xb = xrow + (t + 2) * 256;
                #pragma unroll
                for (int k = 0; k < 16; k++)
                    pf[k] = __ldcs(xb + cl + (k << 4));
            }
        }
    }
    __syncthreads();

    // ---- layer 2: 512 -> 128 (4 outputs/warp) ----
    #pragma unroll
    for (int j = 0; j < 4; j++) {
        int o = (g << 2) + j;
        int seg = SEG_W2 + o;
        int p0 = s_off[seg], p1 = s_off[seg + 1];
        int is0 = 0, is1 = 0;
        for (int p = p0; p < p1; p += 4) {
            uint2 pk = *(const uint2*)(lst + p);
            unsigned e0 = pk.x & 0xffffu, e1 = pk.x >> 16;
            unsigned e2 = pk.y & 0xffffu, e3 = pk.y >> 16;
            unsigned c0 = *(const unsigned short*)(h1s + (e0 >> 2) * 66 + r2);
            unsigned c1 = *(const unsigned short*)(h1s + (e1 >> 2) * 66 + r2);
            unsigned c2 = *(const unsigned short*)(h1s + (e2 >> 2) * 66 + r2);
            unsigned c3 = *(const unsigned short*)(h1s + (e3 >> 2) * 66 + r2);
            is0 += csel(e0 & 3u, (int)(c0 & 0xffu)) + csel(e1 & 3u, (int)(c1 & 0xffu))
                 + csel(e2 & 3u, (int)(c2 & 0xffu)) + csel(e3 & 3u, (int)(c3 & 0xffu));
            is1 += csel(e0 & 3u, (int)(c0 >> 8)) + csel(e1 & 3u, (int)(c1 >> 8))
                 + csel(e2 & 3u, (int)(c2 >> 8)) + csel(e3 & 3u, (int)(c3 >> 8));
        }
        float bv = b2[o];
        unsigned q0 = (unsigned)(int)quant_relu_q(fmaf((float)is0 * ACTS, s2, bv));
        unsigned q1 = (unsigned)(int)quant_relu_q(fmaf((float)is1 * ACTS, s2, bv));
        *(unsigned short*)(h2s + o * 66 + r2) = (unsigned short)(q0 | (q1 << 8));
    }
    __syncthreads();

    // ---- layer 3: 128 -> 64 (2 outputs/warp) ----
    #pragma unroll
    for (int j = 0; j < 2; j++) {
        int o = (g << 1) + j;
        int seg = SEG_W3 + o;
        int p0 = s_off[seg], p1 = s_off[seg + 1];
        int is0 = 0, is1 = 0;
        for (int p = p0; p < p1; p += 4) {
            uint2 pk = *(const uint2*)(lst + p);
            unsigned e0 = pk.x & 0xffffu, e1 = pk.x >> 16;
            unsigned e2 = pk.y & 0xffffu, e3 = pk.y >> 16;
            unsigned c0 = *(const unsigned short*)(h2s + (e0 >> 2) * 66 + r2);
            unsigned c1 = *(const unsigned short*)(h2s + (e1 >> 2) * 66 + r2);
            unsigned c2 = *(const unsigned short*)(h2s + (e2 >> 2) * 66 + r2);
            unsigned c3 = *(const unsigned short*)(h2s + (e3 >> 2) * 66 + r2);
            is0 += csel(e0 & 3u, (int)(c0 & 0xffu)) + csel(e1 & 3u, (int)(c1 & 0xffu))
                 + csel(e2 & 3u, (int)(c2 & 0xffu)) + csel(e3 & 3u, (int)(c3 & 0xffu));
            is1 += csel(e0 & 3u, (int)(c0 >> 8)) + csel(e1 & 3u, (int)(c1 >> 8))
                 + csel(e2 & 3u, (int)(c2 >> 8)) + csel(e3 & 3u, (int)(c3 >> 8));
        }
        float bv = b3[o];
        unsigned q0 = (unsigned)(int)quant_relu_q(fmaf((float)is0 * ACTS, s3, bv));
        unsigned q1 = (unsigned)(int)quant_relu_q(fmaf((float)is1 * ACTS, s3, bv));
        *(unsigned short*)(h3s + o * 66 + r2) = (unsigned short)(q0 | (q1 << 8));
    }
    __syncthreads();

    // ---- output layer: 64 -> 128 (4 outputs/warp), no bias ----
    #pragma unroll
    for (int j = 0; j < 4; j++) {
        int o = (g << 2) + j;
        int seg = SEG_WOUT + o;
        int p0 = s_off[seg], p1 = s_off[seg + 1];
        int is0 = 0, is1 = 0;
        for (int p = p0; p < p1; p += 4) {
            uint2 pk = *(const uint2*)(lst + p);
            unsigned e0 = pk.x & 0xffffu, e1 = pk.x >> 16;
            unsigned e2 = pk.y & 0xffffu, e3 = pk.y >> 16;
            unsigned c0 = *(const unsigned short*)(h3s + (e0 >> 2) * 66 + r2);
            unsigned c1 = *(const unsigned short*)(h3s + (e1 >> 2) * 66 + r2);
            unsigned c2 = *(const unsigned short*)(h3s + (e2 >> 2) * 66 + r2);
            unsigned c3 = *(const unsigned short*)(h3s + (e3 >> 2) * 66 + r2);
            is0 += csel(e0 & 3u, (int)(c0 & 0xffu)) + csel(e1 & 3u, (int)(c1 & 0xffu))
                 + csel(e2 & 3u, (int)(c2 & 0xffu)) + csel(e3 & 3u, (int)(c3 & 0xffu));
            is1 += csel(e0 & 3u, (int)(c0 >> 8)) + csel(e1 & 3u, (int)(c1 >> 8))
                 + csel(e2 & 3u, (int)(c2 >> 8)) + csel(e3 & 3u, (int)(c3 >> 8));
        }
        outs[(r2 + 0) * 132 + o] = ((float)is0 * ACTS) * s4;
        outs[(r2 + 1) * 132 + o] = ((float)is1 * ACTS) * s4;
    }
    __syncthreads();

    // coalesced float4 store: 64 rows x 128 cols
    #pragma unroll
    for (int k = 0; k < 2; k++) {
        int qi = tid + (k << 10);
        int rr = qi >> 5, c4 = qi & 31;
        float4 v = *(const float4*)&outs[rr * 132 + (c4 << 2)];
        *(float4*)&out[(size_t)(row0 + rr) * 128 + (c4 << 2)] = v;
    }
}

__global__ void __launch_bounds__(THREADS, 1) mlp_main(
    const float* __restrict__ x,
    const float* __restrict__ b1a, const float* __restrict__ b1b,
    const float* __restrict__ b2,  const float* __restrict__ b3,
    float* __restrict__ out)
{
    extern __shared__ unsigned char smem[];
    int*   s_off  = (int*)(smem + 181632);
    short* s_list = (short*)(smem + 187016);

    const int tid = threadIdx.x;
    const int row0 = blockIdx.x << 6;

    for (int i = tid; i <= NSEG; i += THREADS) s_off[i] = d_off[i];
    const int total = d_off[NSEG];
    const bool use_sm = (total <= LIST_CAP);
    if (use_sm)
        for (int i = tid; i < total; i += THREADS) s_list[i] = d_list[i];
    __syncthreads();

    if (use_sm)
        mlp_body<true>(smem, x, b1a, b1b, b2, b3, out, row0);
    else
        mlp_body<false>(smem, x, b1a, b1b, b2, b3, out, row0);
}

// ---------------- launch ----------------
extern "C" void kernel_launch(void* const* d_in, const int* in_sizes, int n_in,
                              void* d_out, int out_size)
{
    const float* x    = (const float*)d_in[0];
    const float* W1a  = (const float*)d_in[1];
    const float* b1a  = (const float*)d_in[2];
    const float* W1b  = (const float*)d_in[3];
    const float* b1b  = (const float*)d_in[4];
    const float* W2   = (const float*)d_in[5];
    const float* b2   = (const float*)d_in[6];
    const float* W3   = (const float*)d_in[7];
    const float* b3   = (const float*)d_in[8];
    const float* Wout = (const float*)d_in[9];
    float* out = (float*)d_out;

    prep_scale<<<160, 256>>>(W1a, W1b, W2, W3, Wout);
    prep_count<<<NSEG / 8, 256>>>(W1a, W1b, W2, W3, Wout);
    prep_scanfill<<<148, 256>>>(W1a, W1b, W2, W3, Wout);

    cudaFuncSetAttribute(mlp_main, cudaFuncAttributeMaxDynamicSharedMemorySize, SMEM_BYTES);
    mlp_main<<<GRID, THREADS, SMEM_BYTES>>>(x, b1a, b1b, b2, b3, out);
}